// round 12
// baseline (speedup 1.0000x reference)
#include <cuda_runtime.h>
#include <math.h>

#define BB 64
#define TT 256
#define FF 64
#define UU 512
#define GG 2048      // 4*UU
#define NBLK 128
#define NTHR 512
#define CU 4         // units per block
#define NC 16        // gate-columns per block
#define NW 16        // warps (k split 16 ways)
#define KW 32        // k per warp
#define K8 8         // k per cp.async group
#define NG 4         // groups per warp (KW/K8)
#define HR 68        // staged h row stride (floats)

// ---- static device scratch (no cudaMalloc anywhere) ----
__device__ __align__(256) float g_hsT[(size_t)TT * UU * BB]; // h: [(t*512+u)*64+b]
__device__ float g_coef[TT];
__device__ float g_shift[TT];
__device__ float g_sumW;
__device__ unsigned g_cnt = 0;
__device__ unsigned g_gen = 0;                // reset every launch by prep

__device__ __forceinline__ float sigmoidf_(float x) { return 1.f / (1.f + expf(-x)); }

// packed fp32x2 FMA (Blackwell)
__device__ __forceinline__ unsigned long long fma2(unsigned long long a,
                                                   unsigned long long b,
                                                   unsigned long long c) {
    unsigned long long d;
    asm("fma.rn.f32x2 %0, %1, %2, %3;" : "=l"(d) : "l"(a), "l"(b), "l"(c));
    return d;
}
__device__ __forceinline__ unsigned long long pack2(float v) {
    unsigned long long p;
    unsigned u = __float_as_uint(v);
    asm("mov.b64 %0, {%1, %1};" : "=l"(p) : "r"(u));
    return p;
}
__device__ __forceinline__ unsigned ld_acq_gpu(const unsigned* p) {
    unsigned v;
    asm volatile("ld.acquire.gpu.global.u32 %0, [%1];" : "=r"(v) : "l"(p) : "memory");
    return v;
}
__device__ __forceinline__ unsigned atom_add_rel_gpu(unsigned* p, unsigned v) {
    unsigned old;
    asm volatile("atom.release.gpu.global.add.u32 %0, [%1], %2;"
                 : "=r"(old) : "l"(p), "r"(v) : "memory");
    return old;
}
__device__ __forceinline__ void st_rel_gpu(unsigned* p, unsigned v) {
    asm volatile("st.release.gpu.global.u32 [%0], %1;" :: "l"(p), "r"(v) : "memory");
}
__device__ __forceinline__ void cp_async16(float* smem_dst, const void* gmem_src) {
    unsigned s = (unsigned)__cvta_generic_to_shared(smem_dst);
    asm volatile("cp.async.cg.shared.global [%0], [%1], 16;\n" :: "r"(s), "l"(gmem_src));
}
#define CP_COMMIT() asm volatile("cp.async.commit_group;" ::: "memory")
#define CP_WAIT_1() asm volatile("cp.async.wait_group 1;" ::: "memory")
#define CP_WAIT_0() asm volatile("cp.async.wait_group 0;" ::: "memory")

// no-op pads so ncu's fixed capture slot (-s 5) lands on lstm_persist
__global__ void pad_kernel() {}

// ---------------------------------------------------------------------------
// prep: coef/shift/sumW; block TT also resets grid-barrier state so the
// generation at LSTM step t is exactly t on every launch/replay.
// ---------------------------------------------------------------------------
__global__ void prep_kernel(const float* __restrict__ attW,
                            const float* __restrict__ attb,
                            const float* __restrict__ outW)
{
    __shared__ float red[256];
    int tid = threadIdx.x;
    if (blockIdx.x < TT) {
        int t = blockIdx.x;
        float s = 0.f;
        for (int j = tid; j < t; j += 256) s += attW[t * TT + j];
        red[tid] = s;
        __syncthreads();
        for (int off = 128; off > 0; off >>= 1) {
            if (tid < off) red[tid] += red[tid + off];
            __syncthreads();
        }
        if (tid == 0) {
            g_coef[t]  = (t == 0) ? 1.f : red[0];
            g_shift[t] = (t == 0) ? 0.f : attb[t];
        }
    } else {
        if (tid == 0) { g_cnt = 0u; g_gen = 0u; }
        red[tid] = outW[tid] + outW[tid + 256];
        __syncthreads();
        for (int off = 128; off > 0; off >>= 1) {
            if (tid < off) red[tid] += red[tid + off];
            __syncthreads();
        }
        if (tid == 0) g_sumW = red[0];
    }
}

// ---------------------------------------------------------------------------
// Persistent LSTM. 128 blocks, 512 threads (16 warps = 4/SMSP, k split 16x).
// Warp: full 16-col x 64-batch tile for its 32 k; thread: 4 cols x 8 batches
// (16 f32x2 accumulators). w quad-packed in smem (1 LDS.128/k + ALU packs).
// h(t-1): per-warp PRIVATE cp.async double-buffered smem slab, 4 groups of
// 8 k, pipelined one group ahead -> L2 latency lives in the async engine,
// zero prefetch registers, inner loop is pure LDS(29cyc)+FFMA2.
// Grid barrier: release-atomic arrive / acquire-load wait (gen == t).
// ---------------------------------------------------------------------------
// smem (floats):
//   w4  [512][16]        =  8192 (32 KB)
//   wx4 [64][16]         =  1024 (4 KB)
//   sx2 [64][64]         =  4096 (16 KB)
//   sg  [16][16][68]     = 17408 (68 KB)
//   sg2 [16][68]         =  1088 (4.25 KB)
//   hst [16][2][8][68]   = 17408 (68 KB)
#define OFF_W4   0
#define OFF_WX4  (UU * NC)
#define OFF_SX   (OFF_WX4 + FF * NC)
#define OFF_SG   (OFF_SX + FF * BB)
#define OFF_SG2  (OFF_SG + NW * NC * 68)
#define OFF_HST  (OFF_SG2 + NC * 68)
#define SMEM_FLOATS (OFF_HST + NW * 2 * K8 * HR)

__global__ void __launch_bounds__(NTHR, 1)
lstm_persist(const float* __restrict__ x,     // (B,T,F)
             const float* __restrict__ Wk,    // (F,4U)
             const float* __restrict__ Rk,    // (U,4U)
             const float* __restrict__ bias)  // (4U)
{
    extern __shared__ float smem[];
    float* w4  = smem + OFF_W4;
    float* wx4 = smem + OFF_WX4;
    float* sx2 = smem + OFF_SX;
    float* sg  = smem + OFF_SG;
    float* sg2 = smem + OFF_SG2;
    float* hst = smem + OFF_HST;

    const int tid = threadIdx.x;
    const int bid = blockIdx.x;
    const int u0  = bid * CU;

    // ---- one-time weight staging (quad-packed scalar) ----
    for (int idx = tid; idx < UU * NC; idx += NTHR) {
        int k = idx >> 4, m = idx & 15;
        int c = (m >> 2) + ((m & 3) << 2);          // col for slot m
        int gcol = (c >> 2) * UU + u0 + (c & 3);
        w4[k * 16 + m] = Rk[(size_t)k * GG + gcol];
    }
    for (int idx = tid; idx < FF * NC; idx += NTHR) {
        int f = idx >> 4, m = idx & 15;
        int c = (m >> 2) + ((m & 3) << 2);
        int gcol = (c >> 2) * UU + u0 + (c & 3);
        wx4[f * 16 + m] = Wk[(size_t)f * GG + gcol];
    }

    // GEMM identity
    const int wid  = tid >> 5;        // warp 0..15 -> k range [wid*32, ..)
    const int lane = tid & 31;
    const int cq   = lane >> 3;       // 0..3: cols {cq, cq+4, cq+8, cq+12}
    const int bo   = lane & 7;        // 0..7: batches [bo*8, bo*8+8)
    const int kb   = wid * KW;
    const int b0   = bo * 8;

    // cp.async lane mapping: per round r, lane covers (k8 = 2r + cpk8, 4 floats)
    const int cpk8 = lane >> 4;       // 0/1
    const int cpb4 = (lane & 15) << 2;
    float* slab = hst + (size_t)wid * (2 * K8 * HR);

    // stage-1 reduction identity: col rc, batch pair rb
    const int rc = tid & 15;          // 0..15
    const int rb = (tid >> 4) * 2;    // 0,2,...,62

    // pointwise identity (tid < 256): unit pj, batch pb; bias preloaded
    const int pj = (tid >> 6) & 3;
    const int pb = tid & 63;
    const float bi0 = bias[0 * UU + u0 + pj];
    const float bi1 = bias[1 * UU + u0 + pj];
    const float bi2 = bias[2 * UU + u0 + pj];
    const float bi3 = bias[3 * UU + u0 + pj];
    float creg = 0.f;

    const float4* wp  = (const float4*)w4 + (size_t)kb * 4 + cq;
    const float4* wxp = (const float4*)wx4 + (size_t)(wid * 4) * 4 + cq;

    __syncthreads();

    for (int t = 0; t < TT; ++t) {
        // ---- stage x_t transposed (hides barrier propagation) ----
        for (int i = tid; i < (BB * FF) / 4; i += NTHR) {
            int b  = i & 63;
            int f0 = (i >> 6) << 2;
            float4 xv = *(const float4*)(x + ((size_t)b * TT + t) * FF + f0);
            sx2[(f0 + 0) * 64 + b] = xv.x;
            sx2[(f0 + 1) * 64 + b] = xv.y;
            sx2[(f0 + 2) * 64 + b] = xv.z;
            sx2[(f0 + 3) * 64 + b] = xv.w;
        }
        __syncthreads();

        // ---- wait: generation must reach t (h(t-1) released) ----
        if (t > 0) {
            if (tid == 0) {
                while (ld_acq_gpu(&g_gen) < (unsigned)t) { }
            }
            __syncthreads();
        }

        const float* hsrc = g_hsT + ((size_t)(t - 1) * UU + kb) * BB;

        // ---- issue cp.async group 0 immediately (x-proj hides latency) ----
        if (t > 0) {
            #pragma unroll
            for (int r = 0; r < 4; ++r) {
                int k8 = r * 2 + cpk8;
                cp_async16(slab + k8 * HR + cpb4, hsrc + k8 * 64 + cpb4);
            }
            CP_COMMIT();
        }

        // accumulators: [col j][batch pair p]
        unsigned long long a[4][4];
        #pragma unroll
        for (int j = 0; j < 4; ++j)
            #pragma unroll
            for (int p = 0; p < 4; ++p) a[j][p] = 0ull;

        // ---- input projection: this warp's 4 f (hides group-0 latency) ----
        {
            const float* xp = sx2 + (wid * 4) * 64 + b0;
            #pragma unroll
            for (int f = 0; f < 4; ++f) {
                float4 wq = wxp[f * 4];
                ulonglong2 xa = *(const ulonglong2*)(xp + f * 64);
                ulonglong2 xb = *(const ulonglong2*)(xp + f * 64 + 4);
                unsigned long long w0 = pack2(wq.x);
                unsigned long long w1 = pack2(wq.y);
                unsigned long long w2 = pack2(wq.z);
                unsigned long long w3 = pack2(wq.w);
                a[0][0] = fma2(xa.x, w0, a[0][0]); a[0][1] = fma2(xa.y, w0, a[0][1]);
                a[0][2] = fma2(xb.x, w0, a[0][2]); a[0][3] = fma2(xb.y, w0, a[0][3]);
                a[1][0] = fma2(xa.x, w1, a[1][0]); a[1][1] = fma2(xa.y, w1, a[1][1]);
                a[1][2] = fma2(xb.x, w1, a[1][2]); a[1][3] = fma2(xb.y, w1, a[1][3]);
                a[2][0] = fma2(xa.x, w2, a[2][0]); a[2][1] = fma2(xa.y, w2, a[2][1]);
                a[2][2] = fma2(xb.x, w2, a[2][2]); a[2][3] = fma2(xb.y, w2, a[2][3]);
                a[3][0] = fma2(xa.x, w3, a[3][0]); a[3][1] = fma2(xa.y, w3, a[3][1]);
                a[3][2] = fma2(xb.x, w3, a[3][2]); a[3][3] = fma2(xb.y, w3, a[3][3]);
            }
        }

        // ---- recurrent projection: 4 groups of 8 k, cp.async pipelined ----
        if (t > 0) {
            #pragma unroll
            for (int g = 0; g < NG; ++g) {
                if (g + 1 < NG) {
                    float* dbuf = slab + ((g + 1) & 1) * (K8 * HR);
                    const float* src = hsrc + (size_t)((g + 1) * K8) * 64;
                    #pragma unroll
                    for (int r = 0; r < 4; ++r) {
                        int k8 = r * 2 + cpk8;
                        cp_async16(dbuf + k8 * HR + cpb4, src + k8 * 64 + cpb4);
                    }
                    CP_COMMIT();
                    CP_WAIT_1();
                } else {
                    CP_WAIT_0();
                }
                __syncwarp();

                const float* cbuf = slab + (g & 1) * (K8 * HR) + b0;
                #pragma unroll
                for (int k8 = 0; k8 < K8; ++k8) {
                    float4 wq = wp[(size_t)(g * K8 + k8) * 4];
                    ulonglong2 ca = *(const ulonglong2*)(cbuf + k8 * HR);
                    ulonglong2 cb = *(const ulonglong2*)(cbuf + k8 * HR + 4);
                    unsigned long long w0 = pack2(wq.x);
                    unsigned long long w1 = pack2(wq.y);
                    unsigned long long w2 = pack2(wq.z);
                    unsigned long long w3 = pack2(wq.w);
                    a[0][0] = fma2(ca.x, w0, a[0][0]); a[0][1] = fma2(ca.y, w0, a[0][1]);
                    a[0][2] = fma2(cb.x, w0, a[0][2]); a[0][3] = fma2(cb.y, w0, a[0][3]);
                    a[1][0] = fma2(ca.x, w1, a[1][0]); a[1][1] = fma2(ca.y, w1, a[1][1]);
                    a[1][2] = fma2(cb.x, w1, a[1][2]); a[1][3] = fma2(cb.y, w1, a[1][3]);
                    a[2][0] = fma2(ca.x, w2, a[2][0]); a[2][1] = fma2(ca.y, w2, a[2][1]);
                    a[2][2] = fma2(cb.x, w2, a[2][2]); a[2][3] = fma2(cb.y, w2, a[2][3]);
                    a[3][0] = fma2(ca.x, w3, a[3][0]); a[3][1] = fma2(ca.y, w3, a[3][1]);
                    a[3][2] = fma2(cb.x, w3, a[3][2]); a[3][3] = fma2(cb.y, w3, a[3][3]);
                }
                __syncwarp();   // all lanes done reading buf before next overwrite
            }
        }

        // ---- write partials: sg[wid][c][b] ----
        #pragma unroll
        for (int j = 0; j < 4; ++j) {
            int c = cq + 4 * j;
            float* dst = sg + (size_t)(wid * NC + c) * 68 + b0;
            *(ulonglong2*)(dst)     = make_ulonglong2(a[j][0], a[j][1]);
            *(ulonglong2*)(dst + 4) = make_ulonglong2(a[j][2], a[j][3]);
        }
        __syncthreads();

        // ---- stage 1: sum 16 k-partials (512 threads, 2 floats each) ----
        {
            float2 s = make_float2(0.f, 0.f);
            #pragma unroll
            for (int w = 0; w < NW; ++w) {
                float2 v = *(const float2*)(sg + (size_t)(w * NC + rc) * 68 + rb);
                s.x += v.x; s.y += v.y;
            }
            *(float2*)(sg2 + rc * 68 + rb) = s;
        }
        __syncthreads();

        // ---- stage 2 pointwise (tid < 256): gates + state update ----
        if (tid < 256) {
            float iv = bi0 + sg2[(0 * 4 + pj) * 68 + pb];
            float fv = bi1 + sg2[(1 * 4 + pj) * 68 + pb];
            float gv = bi2 + sg2[(2 * 4 + pj) * 68 + pb];
            float ov = bi3 + sg2[(3 * 4 + pj) * 68 + pb];
            creg = sigmoidf_(fv) * creg + sigmoidf_(iv) * tanhf(gv);
            float hval = sigmoidf_(ov) * tanhf(creg);
            g_hsT[((size_t)t * UU + u0 + pj) * 64 + pb] = hval;
        }

        // ---- arrive: release h(t) ----
        if (t + 1 < TT) {
            __syncthreads();
            if (tid == 0) {
                unsigned old = atom_add_rel_gpu(&g_cnt, 1u);
                if (old == (unsigned)(NBLK - 1)) {
                    g_cnt = 0u;                       // ordered before release
                    st_rel_gpu(&g_gen, (unsigned)(t + 1));
                }
            }
        }
    }
}

// ---------------------------------------------------------------------------
__global__ void out_kernel(const float* __restrict__ outW,
                           const float* __restrict__ outb,
                           float* __restrict__ y)
{
    int t  = blockIdx.x;
    int b  = threadIdx.x & 63;
    int ug = threadIdx.x >> 6;   // 0..3
    float s = 0.f;
    const float* base = g_hsT + (size_t)t * UU * BB;
    #pragma unroll 4
    for (int u = ug * 128; u < ug * 128 + 128; ++u)
        s += base[(size_t)u * 64 + b] * outW[u];
    __shared__ float red[4][64];
    red[ug][b] = s;
    __syncthreads();
    if (ug == 0) {
        float v = red[0][b] + red[1][b] + red[2][b] + red[3][b];
        v = g_coef[t] * v + g_shift[t] * g_sumW + outb[0];
        y[b * TT + t] = 1.f / (1.f + expf(-v));
    }
}

// ---------------------------------------------------------------------------
extern "C" void kernel_launch(void* const* d_in, const int* in_sizes, int n_in,
                              void* d_out, int out_size)
{
    (void)in_sizes; (void)n_in; (void)out_size;
    const float* inputs = (const float*)d_in[0];
    const float* kernel = (const float*)d_in[1];
    const float* rec    = (const float*)d_in[2];
    const float* bias   = (const float*)d_in[3];
    const float* attW   = (const float*)d_in[4];
    const float* attb   = (const float*)d_in[5];
    const float* outW   = (const float*)d_in[6];
    const float* outb   = (const float*)d_in[7];
    float* y = (float*)d_out;

    static int smem_set = 0;
    size_t smem_bytes = SMEM_FLOATS * sizeof(float);   // ~192 KB
    if (!smem_set) {
        cudaFuncSetAttribute(lstm_persist,
                             cudaFuncAttributeMaxDynamicSharedMemorySize,
                             (int)smem_bytes);
        smem_set = 1;
    }

    // pads so lstm_persist lands on ncu's capture slot (-s 5)
    pad_kernel<<<1, 32>>>();
    pad_kernel<<<1, 32>>>();
    prep_kernel<<<TT + 1, 256>>>(attW, attb, outW);    // also resets barrier state
    lstm_persist<<<NBLK, NTHR, smem_bytes>>>(inputs, kernel, rec, bias);
    out_kernel<<<TT, 256>>>(outW, outb, y);
}